// round 1
// baseline (speedup 1.0000x reference)
#include <cuda_runtime.h>

// Problem constants (fixed shapes per reference: N=8192, D=1024, 128 classes)
#define NMAX 8192
#define MARGIN 1.0f
#define EPS 1e-6f

// Scratch: Gram matrix + row stats. Static __device__ arrays (no allocation).
__device__ float g_G[(size_t)NMAX * (size_t)NMAX];   // 256 MB
__device__ float g_sq[NMAX];                         // ||e_i||^2
__device__ float g_s[NMAX];                          // sum_k e_ik

// ---------------------------------------------------------------------------
// Row stats: sq[i] = sum e^2, s[i] = sum e. One block per row.
// ---------------------------------------------------------------------------
__global__ void __launch_bounds__(256) rowstats_kernel(const float* __restrict__ E,
                                                       int N, int D) {
    int i = blockIdx.x;
    const float* row = E + (size_t)i * D;
    float a = 0.0f, b = 0.0f;
    for (int k = threadIdx.x; k < D; k += blockDim.x) {
        float v = row[k];
        a = fmaf(v, v, a);
        b += v;
    }
#pragma unroll
    for (int off = 16; off > 0; off >>= 1) {
        a += __shfl_down_sync(0xffffffffu, a, off);
        b += __shfl_down_sync(0xffffffffu, b, off);
    }
    __shared__ float sa[8], sb[8];
    int w = threadIdx.x >> 5, l = threadIdx.x & 31;
    if (l == 0) { sa[w] = a; sb[w] = b; }
    __syncthreads();
    if (threadIdx.x == 0) {
        float A = 0.0f, B = 0.0f;
        int nw = blockDim.x >> 5;
        for (int x = 0; x < nw; x++) { A += sa[x]; B += sb[x]; }
        g_sq[i] = A;
        g_s[i] = B;
    }
}

// ---------------------------------------------------------------------------
// Symmetric SGEMM: G = E * E^T. Only lower-triangular tile pairs computed,
// the transpose tile is mirror-written. 128x128 block tile, 8x8 per thread,
// BK=8, 256 threads, single-stage smem with register prefetch of next K-slab.
// Requires N % 128 == 0, D % 8 == 0.
// ---------------------------------------------------------------------------
__global__ void __launch_bounds__(256) syrk_kernel(const float* __restrict__ E,
                                                   int N, int D) {
    int bi = blockIdx.y, bj = blockIdx.x;
    if (bj > bi) return;

    __shared__ float As[8][128];
    __shared__ float Bs[8][128];

    int tid = threadIdx.x;
    int lm = tid >> 1;            // 0..127 row within tile
    int lk = (tid & 1) << 2;      // 0 or 4

    const float* Ag = E + (size_t)(bi * 128 + lm) * D + lk;
    const float* Bg = E + (size_t)(bj * 128 + lm) * D + lk;

    int tx = tid & 15;            // 0..15 -> 8-col group
    int ty = tid >> 4;            // 0..15 -> 8-row group

    float acc[8][8];
#pragma unroll
    for (int m = 0; m < 8; m++)
#pragma unroll
        for (int n = 0; n < 8; n++) acc[m][n] = 0.0f;

    float4 a4 = *(const float4*)Ag;
    float4 b4 = *(const float4*)Bg;

    for (int k0 = 0; k0 < D; k0 += 8) {
        __syncthreads();
        As[lk + 0][lm] = a4.x; As[lk + 1][lm] = a4.y;
        As[lk + 2][lm] = a4.z; As[lk + 3][lm] = a4.w;
        Bs[lk + 0][lm] = b4.x; Bs[lk + 1][lm] = b4.y;
        Bs[lk + 2][lm] = b4.z; Bs[lk + 3][lm] = b4.w;
        __syncthreads();

        if (k0 + 8 < D) {                      // prefetch next K slab
            a4 = *(const float4*)(Ag + k0 + 8);
            b4 = *(const float4*)(Bg + k0 + 8);
        }

#pragma unroll
        for (int k = 0; k < 8; k++) {
            float af[8], bf[8];
            *(float4*)&af[0] = *(const float4*)&As[k][ty * 8];
            *(float4*)&af[4] = *(const float4*)&As[k][ty * 8 + 4];
            *(float4*)&bf[0] = *(const float4*)&Bs[k][tx * 8];
            *(float4*)&bf[4] = *(const float4*)&Bs[k][tx * 8 + 4];
#pragma unroll
            for (int m = 0; m < 8; m++)
#pragma unroll
                for (int n = 0; n < 8; n++)
                    acc[m][n] = fmaf(af[m], bf[n], acc[m][n]);
        }
    }

    int row0 = bi * 128 + ty * 8;
    int col0 = bj * 128 + tx * 8;
#pragma unroll
    for (int m = 0; m < 8; m++) {
        *(float4*)&g_G[(size_t)(row0 + m) * N + col0] =
            make_float4(acc[m][0], acc[m][1], acc[m][2], acc[m][3]);
        *(float4*)&g_G[(size_t)(row0 + m) * N + col0 + 4] =
            make_float4(acc[m][4], acc[m][5], acc[m][6], acc[m][7]);
    }
    if (bi != bj) {  // mirror tile
#pragma unroll
        for (int n = 0; n < 8; n++) {
            *(float4*)&g_G[(size_t)(col0 + n) * N + row0] =
                make_float4(acc[0][n], acc[1][n], acc[2][n], acc[3][n]);
            *(float4*)&g_G[(size_t)(col0 + n) * N + row0 + 4] =
                make_float4(acc[4][n], acc[5][n], acc[6][n], acc[7][n]);
        }
    }
}

// ---------------------------------------------------------------------------
// Mining + loss. One block (256 threads) per anchor row.
// ds[j] in shared: distance for negatives, -1 sentinel for same-class/self.
// Pass 1: hardest positive (argmax, first-index tie-break like jnp.argmax).
// Pass 2: semi-hard negative (closest with d_p < d < d_p+margin) else hardest
// (closest) negative. Loss term recomputes torch pairwise_distance with EPS.
// ---------------------------------------------------------------------------
__global__ void __launch_bounds__(256) mine_kernel(const int* __restrict__ target,
                                                   int N, int D,
                                                   float* __restrict__ out) {
    int i = blockIdx.x;
    __shared__ float ds[NMAX];
    __shared__ float rv[256];  __shared__ int rj[256];
    __shared__ float rv2[256]; __shared__ int rj2[256];

    int tid = threadIdx.x;
    int ti = target[i];
    float sqi = g_sq[i];
    const float* Gi = g_G + (size_t)i * N;

    // Pass 1: compute distances, stash negatives, track hardest positive.
    float bp = -1e30f; int bpj = 0x7fffffff;
    for (int j = tid; j < N; j += 256) {
        float d2 = fmaxf(sqi + g_sq[j] - 2.0f * Gi[j], 0.0f);
        float d = sqrtf(d2);
        if (target[j] == ti) {
            ds[j] = -1.0f;  // not a negative
            if (j != i) {
                if (d > bp || (d == bp && j < bpj)) { bp = d; bpj = j; }
            }
        } else {
            ds[j] = d;
        }
    }
    rv[tid] = bp; rj[tid] = bpj;
    __syncthreads();
    for (int st = 128; st > 0; st >>= 1) {
        if (tid < st) {
            float v = rv[tid + st]; int j = rj[tid + st];
            if (v > rv[tid] || (v == rv[tid] && j < rj[tid])) { rv[tid] = v; rj[tid] = j; }
        }
        __syncthreads();
    }
    float d_p = rv[0];
    int pos = rj[0];
    __syncthreads();

    // Pass 2: negatives. m1 = overall min, m2 = min among d > d_p.
    float m1 = 1e30f; int j1 = 0x7fffffff;
    float m2 = 1e30f; int j2 = 0x7fffffff;
    for (int j = tid; j < N; j += 256) {
        float d = ds[j];
        if (d >= 0.0f) {
            if (d < m1 || (d == m1 && j < j1)) { m1 = d; j1 = j; }
            if (d > d_p) {
                if (d < m2 || (d == m2 && j < j2)) { m2 = d; j2 = j; }
            }
        }
    }
    rv[tid] = m1; rj[tid] = j1; rv2[tid] = m2; rj2[tid] = j2;
    __syncthreads();
    for (int st = 128; st > 0; st >>= 1) {
        if (tid < st) {
            float v = rv[tid + st]; int j = rj[tid + st];
            if (v < rv[tid] || (v == rv[tid] && j < rj[tid])) { rv[tid] = v; rj[tid] = j; }
            v = rv2[tid + st]; j = rj2[tid + st];
            if (v < rv2[tid] || (v == rv2[tid] && j < rj2[tid])) { rv2[tid] = v; rj2[tid] = j; }
        }
        __syncthreads();
    }

    if (tid == 0) {
        if (pos == 0x7fffffff) pos = 0;  // degenerate (no positive) fallback; matches argmax-of-all--INF = 0
        int neg = (rv2[0] < d_p + MARGIN) ? rj2[0] : rj[0];
        if (neg == 0x7fffffff) neg = 0;

        float si = g_s[i];
        float epsC = (float)D * EPS * EPS;

        float d2p = sqi + g_sq[pos] - 2.0f * Gi[pos];
        float dp = sqrtf(fmaxf(d2p + 2.0f * EPS * (si - g_s[pos]) + epsC, 0.0f));
        float d2n = sqi + g_sq[neg] - 2.0f * Gi[neg];
        float dn = sqrtf(fmaxf(d2n + 2.0f * EPS * (si - g_s[neg]) + epsC, 0.0f));

        float term = fmaxf(dp - dn + MARGIN, 0.0f);
        atomicAdd(out, term / (float)N);
    }
}

__global__ void zero_kernel(float* out, int n) {
    int idx = blockIdx.x * blockDim.x + threadIdx.x;
    if (idx < n) out[idx] = 0.0f;
}

// ---------------------------------------------------------------------------
extern "C" void kernel_launch(void* const* d_in, const int* in_sizes, int n_in,
                              void* d_out, int out_size) {
    const float* E = (const float*)d_in[0];   // embeddings [N, D] fp32
    const int* target = (const int*)d_in[1];  // [N] int32
    float* out = (float*)d_out;

    int N = in_sizes[1];
    int D = in_sizes[0] / N;

    rowstats_kernel<<<N, 256>>>(E, N, D);

    dim3 grid(N / 128, N / 128);
    syrk_kernel<<<grid, 256>>>(E, N, D);

    zero_kernel<<<1, 32>>>(out, out_size);

    mine_kernel<<<N, 256>>>(target, N, D, out);
}

// round 2
// speedup vs baseline: 1.0036x; 1.0036x over previous
#include <cuda_runtime.h>

// Problem constants (fixed shapes per reference: N=8192, D=1024, 128 classes)
#define NMAX 8192
#define MARGIN 1.0f
#define EPS 1e-6f

// Scratch: Gram matrix + row stats. Static __device__ arrays (no allocation).
__device__ float g_G[(size_t)NMAX * (size_t)NMAX];   // 256 MB
__device__ float g_sq[NMAX];                         // ||e_i||^2
__device__ float g_s[NMAX];                          // sum_k e_ik

// ---------------------------------------------------------------------------
// Row stats: sq[i] = sum e^2, s[i] = sum e. One block per row.
// ---------------------------------------------------------------------------
__global__ void __launch_bounds__(256) rowstats_kernel(const float* __restrict__ E,
                                                       int N, int D) {
    int i = blockIdx.x;
    const float* row = E + (size_t)i * D;
    float a = 0.0f, b = 0.0f;
    for (int k = threadIdx.x; k < D; k += blockDim.x) {
        float v = row[k];
        a = fmaf(v, v, a);
        b += v;
    }
#pragma unroll
    for (int off = 16; off > 0; off >>= 1) {
        a += __shfl_down_sync(0xffffffffu, a, off);
        b += __shfl_down_sync(0xffffffffu, b, off);
    }
    __shared__ float sa[8], sb[8];
    int w = threadIdx.x >> 5, l = threadIdx.x & 31;
    if (l == 0) { sa[w] = a; sb[w] = b; }
    __syncthreads();
    if (threadIdx.x == 0) {
        float A = 0.0f, B = 0.0f;
        int nw = blockDim.x >> 5;
        for (int x = 0; x < nw; x++) { A += sa[x]; B += sb[x]; }
        g_sq[i] = A;
        g_s[i] = B;
    }
}

// ---------------------------------------------------------------------------
// Symmetric SGEMM: G = E * E^T. Only lower-triangular tile pairs computed,
// the transpose tile is mirror-written. 128x128 block tile, 8x8 per thread,
// BK=8, 256 threads, single-stage smem with register prefetch of next K-slab.
// Requires N % 128 == 0, D % 8 == 0.
// ---------------------------------------------------------------------------
__global__ void __launch_bounds__(256) syrk_kernel(const float* __restrict__ E,
                                                   int N, int D) {
    int bi = blockIdx.y, bj = blockIdx.x;
    if (bj > bi) return;

    __shared__ float As[8][128];
    __shared__ float Bs[8][128];

    int tid = threadIdx.x;
    int lm = tid >> 1;            // 0..127 row within tile
    int lk = (tid & 1) << 2;      // 0 or 4

    const float* Ag = E + (size_t)(bi * 128 + lm) * D + lk;
    const float* Bg = E + (size_t)(bj * 128 + lm) * D + lk;

    int tx = tid & 15;            // 0..15 -> 8-col group
    int ty = tid >> 4;            // 0..15 -> 8-row group

    float acc[8][8];
#pragma unroll
    for (int m = 0; m < 8; m++)
#pragma unroll
        for (int n = 0; n < 8; n++) acc[m][n] = 0.0f;

    float4 a4 = *(const float4*)Ag;
    float4 b4 = *(const float4*)Bg;

    for (int k0 = 0; k0 < D; k0 += 8) {
        __syncthreads();
        As[lk + 0][lm] = a4.x; As[lk + 1][lm] = a4.y;
        As[lk + 2][lm] = a4.z; As[lk + 3][lm] = a4.w;
        Bs[lk + 0][lm] = b4.x; Bs[lk + 1][lm] = b4.y;
        Bs[lk + 2][lm] = b4.z; Bs[lk + 3][lm] = b4.w;
        __syncthreads();

        if (k0 + 8 < D) {                      // prefetch next K slab
            a4 = *(const float4*)(Ag + k0 + 8);
            b4 = *(const float4*)(Bg + k0 + 8);
        }

#pragma unroll
        for (int k = 0; k < 8; k++) {
            float af[8], bf[8];
            *(float4*)&af[0] = *(const float4*)&As[k][ty * 8];
            *(float4*)&af[4] = *(const float4*)&As[k][ty * 8 + 4];
            *(float4*)&bf[0] = *(const float4*)&Bs[k][tx * 8];
            *(float4*)&bf[4] = *(const float4*)&Bs[k][tx * 8 + 4];
#pragma unroll
            for (int m = 0; m < 8; m++)
#pragma unroll
                for (int n = 0; n < 8; n++)
                    acc[m][n] = fmaf(af[m], bf[n], acc[m][n]);
        }
    }

    int row0 = bi * 128 + ty * 8;
    int col0 = bj * 128 + tx * 8;
#pragma unroll
    for (int m = 0; m < 8; m++) {
        *(float4*)&g_G[(size_t)(row0 + m) * N + col0] =
            make_float4(acc[m][0], acc[m][1], acc[m][2], acc[m][3]);
        *(float4*)&g_G[(size_t)(row0 + m) * N + col0 + 4] =
            make_float4(acc[m][4], acc[m][5], acc[m][6], acc[m][7]);
    }
    if (bi != bj) {  // mirror tile
#pragma unroll
        for (int n = 0; n < 8; n++) {
            *(float4*)&g_G[(size_t)(col0 + n) * N + row0] =
                make_float4(acc[0][n], acc[1][n], acc[2][n], acc[3][n]);
            *(float4*)&g_G[(size_t)(col0 + n) * N + row0 + 4] =
                make_float4(acc[4][n], acc[5][n], acc[6][n], acc[7][n]);
        }
    }
}

// ---------------------------------------------------------------------------
// Mining + loss. One block (256 threads) per anchor row.
// ds[j] in shared: distance for negatives, -1 sentinel for same-class/self.
// Pass 1: hardest positive (argmax, first-index tie-break like jnp.argmax).
// Pass 2: semi-hard negative (closest with d_p < d < d_p+margin) else hardest
// (closest) negative. Loss term recomputes torch pairwise_distance with EPS.
// ---------------------------------------------------------------------------
__global__ void __launch_bounds__(256) mine_kernel(const int* __restrict__ target,
                                                   int N, int D,
                                                   float* __restrict__ out) {
    int i = blockIdx.x;
    __shared__ float ds[NMAX];
    __shared__ float rv[256];  __shared__ int rj[256];
    __shared__ float rv2[256]; __shared__ int rj2[256];

    int tid = threadIdx.x;
    int ti = target[i];
    float sqi = g_sq[i];
    const float* Gi = g_G + (size_t)i * N;

    // Pass 1: compute distances, stash negatives, track hardest positive.
    float bp = -1e30f; int bpj = 0x7fffffff;
    for (int j = tid; j < N; j += 256) {
        float d2 = fmaxf(sqi + g_sq[j] - 2.0f * Gi[j], 0.0f);
        float d = sqrtf(d2);
        if (target[j] == ti) {
            ds[j] = -1.0f;  // not a negative
            if (j != i) {
                if (d > bp || (d == bp && j < bpj)) { bp = d; bpj = j; }
            }
        } else {
            ds[j] = d;
        }
    }
    rv[tid] = bp; rj[tid] = bpj;
    __syncthreads();
    for (int st = 128; st > 0; st >>= 1) {
        if (tid < st) {
            float v = rv[tid + st]; int j = rj[tid + st];
            if (v > rv[tid] || (v == rv[tid] && j < rj[tid])) { rv[tid] = v; rj[tid] = j; }
        }
        __syncthreads();
    }
    float d_p = rv[0];
    int pos = rj[0];
    __syncthreads();

    // Pass 2: negatives. m1 = overall min, m2 = min among d > d_p.
    float m1 = 1e30f; int j1 = 0x7fffffff;
    float m2 = 1e30f; int j2 = 0x7fffffff;
    for (int j = tid; j < N; j += 256) {
        float d = ds[j];
        if (d >= 0.0f) {
            if (d < m1 || (d == m1 && j < j1)) { m1 = d; j1 = j; }
            if (d > d_p) {
                if (d < m2 || (d == m2 && j < j2)) { m2 = d; j2 = j; }
            }
        }
    }
    rv[tid] = m1; rj[tid] = j1; rv2[tid] = m2; rj2[tid] = j2;
    __syncthreads();
    for (int st = 128; st > 0; st >>= 1) {
        if (tid < st) {
            float v = rv[tid + st]; int j = rj[tid + st];
            if (v < rv[tid] || (v == rv[tid] && j < rj[tid])) { rv[tid] = v; rj[tid] = j; }
            v = rv2[tid + st]; j = rj2[tid + st];
            if (v < rv2[tid] || (v == rv2[tid] && j < rj2[tid])) { rv2[tid] = v; rj2[tid] = j; }
        }
        __syncthreads();
    }

    if (tid == 0) {
        if (pos == 0x7fffffff) pos = 0;  // degenerate (no positive) fallback; matches argmax-of-all--INF = 0
        int neg = (rv2[0] < d_p + MARGIN) ? rj2[0] : rj[0];
        if (neg == 0x7fffffff) neg = 0;

        float si = g_s[i];
        float epsC = (float)D * EPS * EPS;

        float d2p = sqi + g_sq[pos] - 2.0f * Gi[pos];
        float dp = sqrtf(fmaxf(d2p + 2.0f * EPS * (si - g_s[pos]) + epsC, 0.0f));
        float d2n = sqi + g_sq[neg] - 2.0f * Gi[neg];
        float dn = sqrtf(fmaxf(d2n + 2.0f * EPS * (si - g_s[neg]) + epsC, 0.0f));

        float term = fmaxf(dp - dn + MARGIN, 0.0f);
        atomicAdd(out, term / (float)N);
    }
}

__global__ void zero_kernel(float* out, int n) {
    int idx = blockIdx.x * blockDim.x + threadIdx.x;
    if (idx < n) out[idx] = 0.0f;
}

// ---------------------------------------------------------------------------
extern "C" void kernel_launch(void* const* d_in, const int* in_sizes, int n_in,
                              void* d_out, int out_size) {
    const float* E = (const float*)d_in[0];   // embeddings [N, D] fp32
    const int* target = (const int*)d_in[1];  // [N] int32
    float* out = (float*)d_out;

    int N = in_sizes[1];
    int D = in_sizes[0] / N;

    rowstats_kernel<<<N, 256>>>(E, N, D);

    dim3 grid(N / 128, N / 128);
    syrk_kernel<<<grid, 256>>>(E, N, D);

    zero_kernel<<<1, 32>>>(out, out_size);

    mine_kernel<<<N, 256>>>(target, N, D, out);
}